// round 17
// baseline (speedup 1.0000x reference)
#include <cuda_runtime.h>
#include <cuda_bf16.h>

// SurvEMD fused forward (math: see prior rounds). Base = R15 (masked
// grid-stride; best kernel 51.2us).
// R16->R17:
//  1. GRID_B = 2220 (= 148 SMs * 15 = 740 resident blocks * 3): exact 3-wave
//     packing at 5 blocks/SM, removing the ceil(2.77)=3 wave-quantization loss
//     (~8%) of the 2048-block grid. Masked grid-stride loop absorbs the
//     ragged 7-vs-8 iteration split.
//  2. Loss chain back to scalar FFMAs (tot-space kept): the f32x2 pk2 MOV
//     overhead ~cancels the packed-op savings; scalar drops the pair
//     constraints.

#define NBINS       64
#define BLOCK_T     256
#define GRID_B      2220
#define MAX_GRID    4096
#define EXP_NEG20   2.0611536e-09f   // expf(-20.0f)
#define FULL        0xFFFFFFFFu

__device__ float    g_partials[MAX_GRID];
__device__ unsigned g_count;         // zero-init; reset by last block each launch

__device__ __forceinline__ float frcp(float x) {
    float r;
    asm("rcp.approx.f32 %0, %1;" : "=f"(r) : "f"(x));
    return r;
}

__global__ __launch_bounds__(BLOCK_T, 5)
void survemd_main(const float* __restrict__ y_hat,
                  const int* __restrict__ t_in,
                  const int* __restrict__ e_in,
                  float* __restrict__ out,
                  int B)
{
    const int lane = threadIdx.x & 31;
    const int s    = lane & 3;    // sub-lane within row (owns f4 indices 4c+s)
    const int g    = lane >> 2;   // row within the warp's 8-row group
    const int wid  = threadIdx.x >> 5;

    const int warpsPerBlock = BLOCK_T / 32;
    const int gwarp   = blockIdx.x * warpsPerBlock + wid;
    const int wstride = GRID_B * warpsPerBlock * 8;     // rows per grid-stride step

    // per-lane element base: jp1(c,i) = (4s + i + 1) + 16c
    const float b0f = (float)(4 * s + 1);
    const float b1f = b0f + 1.0f;
    const float b2f = b0f + 2.0f;
    const float b3f = b0f + 3.0f;

    float acc = 0.0f;

    for (int base = gwarp * 8; base < B; base += wstride) {
        const int   row   = base + g;
        const int   rowc  = min(row, B - 1);
        const float vmask = (row < B) ? 1.0f : 0.0f;

        const int tr = t_in[rowc];
        const int er = e_in[rowc];

        // interleaved float4 loads: f4 index = rowc*16 + 4c + s
        const float4* yrow = (const float4*)y_hat + (size_t)rowc * 16 + s;
        float4 ya[4];
        ya[0] = yrow[0];
        ya[1] = yrow[4];
        ya[2] = yrow[8];
        ya[3] = yrow[12];

        // row params
        const bool  cen = (er == 0);
        const float tf  = (float)tr;
        const float kf  = cen ? (64.0f - tf) : 1.0f;
        const float q1  = frcp(fmaf(64.0f - kf, EXP_NEG20, kf));
        const float q0  = EXP_NEG20 * q1;
        const float dq  = q1 - q0;
        const float thr = cen ? tf : 3.0e38f;
        const float isc = cen ? 0.015625f : 1.0f;
        const float nb  = -tf * isc;
        const float ndqe = cen ? (dq * -64.0f) : -dq;

        // exps + in-lane inclusive partials per 4-element chunk
        float sl[4][4];
        #pragma unroll
        for (int c = 0; c < 4; c++) {
            const float thrc = thr - 16.0f * (float)c;
            float e0 = __expf((b0f > thrc) ? 10.0f : ya[c].x);
            float e1 = __expf((b1f > thrc) ? 10.0f : ya[c].y);
            float e2 = __expf((b2f > thrc) ? 10.0f : ya[c].z);
            float e3 = __expf((b3f > thrc) ? 10.0f : ya[c].w);
            sl[c][0] = e0;
            sl[c][1] = sl[c][0] + e1;
            sl[c][2] = sl[c][1] + e2;
            sl[c][3] = sl[c][2] + e3;
        }

        // exclusive quad prefixes (unnormalized): width-4 shfl scan + carry
        float E[4];
        float carry = 0.0f;
        #pragma unroll
        for (int c = 0; c < 4; c++) {
            float incl = sl[c][3];
            float v = __shfl_up_sync(FULL, incl, 1, 4);
            if (s >= 1) incl += v;
            v = __shfl_up_sync(FULL, incl, 2, 4);
            if (s >= 2) incl += v;
            const float W = __shfl_sync(FULL, incl, 3, 4);   // chunk total
            E[c] = carry + (incl - sl[c][3]);
            carry += W;
        }

        const float tot   = carry;          // row softmax denominator (unnorm)
        const float inv   = frcp(tot);      // off critical path
        const float nq0t  = -q0 * tot;
        const float ndqet = ndqe * tot;

        // loss in tot-space (scalar): m = (E + s) - tot*T ; loss = sum m^2 * inv^2
        float r = 0.0f;
        #pragma unroll
        for (int c = 0; c < 4; c++) {
            const float hq = fmaf(16.0f * (float)c, nq0t, E[c]);
            const float hb = fmaf(16.0f * (float)c, isc, nb);

            const float c0 = __saturatef(fmaf(b0f, isc, hb));
            const float c1 = __saturatef(fmaf(b1f, isc, hb));
            const float c2 = __saturatef(fmaf(b2f, isc, hb));
            const float c3 = __saturatef(fmaf(b3f, isc, hb));

            const float w0 = fmaf(c0, ndqet, fmaf(b0f, nq0t, hq));
            const float w1 = fmaf(c1, ndqet, fmaf(b1f, nq0t, hq));
            const float w2 = fmaf(c2, ndqet, fmaf(b2f, nq0t, hq));
            const float w3 = fmaf(c3, ndqet, fmaf(b3f, nq0t, hq));

            const float m0 = sl[c][0] + w0;
            const float m1 = sl[c][1] + w1;
            const float m2 = sl[c][2] + w2;
            const float m3 = sl[c][3] + w3;

            r = fmaf(m0, m0, r);
            r = fmaf(m1, m1, r);
            r = fmaf(m2, m2, r);
            r = fmaf(m3, m3, r);
        }

        acc = fmaf(vmask, r * (inv * inv), acc);
    }

    // block reduction (warp sum covers all 8 rows' lane partials)
    #pragma unroll
    for (int off = 16; off > 0; off >>= 1)
        acc += __shfl_xor_sync(FULL, acc, off);

    __shared__ float warpSums[BLOCK_T / 32];
    if (lane == 0) warpSums[wid] = acc;
    __syncthreads();

    __shared__ bool isLast;
    if (threadIdx.x == 0) {
        float sm = 0.0f;
        #pragma unroll
        for (int i = 0; i < BLOCK_T / 32; i++) sm += warpSums[i];
        g_partials[blockIdx.x] = sm;
        __threadfence();
        unsigned ticket = atomicAdd(&g_count, 1u);
        isLast = (ticket == (unsigned)(gridDim.x - 1));
    }
    __syncthreads();

    // last block reduces all partials (deterministic order) and resets counter
    if (isLast) {
        float sm = 0.0f;
        for (int i = threadIdx.x; i < GRID_B; i += BLOCK_T)
            sm += ((volatile float*)g_partials)[i];

        #pragma unroll
        for (int off = 16; off > 0; off >>= 1)
            sm += __shfl_xor_sync(FULL, sm, off);

        __shared__ float finalSums[BLOCK_T / 32];
        if (lane == 0) finalSums[wid] = sm;
        __syncthreads();

        if (threadIdx.x == 0) {
            float tot = 0.0f;
            #pragma unroll
            for (int i = 0; i < BLOCK_T / 32; i++) tot += finalSums[i];
            out[0] = tot / (float)B;
            g_count = 0;   // reset for next graph replay
        }
    }
}

extern "C" void kernel_launch(void* const* d_in, const int* in_sizes, int n_in,
                              void* d_out, int out_size)
{
    const float* y_hat = (const float*)d_in[0];
    const int*   t     = (const int*)d_in[1];
    const int*   e     = (const int*)d_in[2];
    float*       out   = (float*)d_out;
    const int B = in_sizes[1];   // element count of t

    survemd_main<<<GRID_B, BLOCK_T>>>(y_hat, t, e, out, B);
}